// round 2
// baseline (speedup 1.0000x reference)
#include <cuda_runtime.h>
#include <cuda_bf16.h>
#include <cstdint>

// ---------------------------------------------------------------------------
// Model: T=50, B=1. VIN=768, VF=128, MIN=2, MF=128, H=256.
//  pre:  f = elu([W1v@v ; W1m@m]) ; Gx[t] = Wih_low[:, :256] @ f[t] + bih_low
//  scan: h1 = GRU([f;h2], h1) with (Wih_low split), h2 = GRU(h1, h2)
//  post: v_n = sigmoid(W2v @ elu(h1[:128])), m_n = tanh(W2m @ elu(h1[128:256]))
// ---------------------------------------------------------------------------

#define TSTEPS 50
#define HSZ    256

__device__ float g_Gx[TSTEPS * 768];   // precomputed input gates for low GRU
__device__ float g_h1[TSTEPS * HSZ];   // h1 per step (scan output)

__device__ __forceinline__ float eluf(float x) { return x > 0.f ? x : expm1f(x); }
__device__ __forceinline__ float sigf(float x) { return 1.f / (1.f + expf(-x)); }

__device__ __forceinline__ void cluster_sync_dev() {
    asm volatile("barrier.cluster.arrive.aligned;\n\t"
                 "barrier.cluster.wait.aligned;" ::: "memory");
}

__device__ __forceinline__ void st_remote_f32(float* local_smem, int rank, float v) {
    uint32_t a = (uint32_t)__cvta_generic_to_shared(local_smem);
    uint32_t ra;
    asm volatile("mapa.shared::cluster.u32 %0, %1, %2;" : "=r"(ra) : "r"(a), "r"(rank));
    asm volatile("st.shared::cluster.f32 [%0], %1;" :: "r"(ra), "f"(v) : "memory");
}

// 256-wide dot of one weight row (smem) against h (in regs: cols 8*lane..8*lane+7).
__device__ __forceinline__ float rowdot(const float* __restrict__ row, int lane,
                                        float4 ha, float4 hb) {
    const float4* r4 = (const float4*)row;
    float4 w0 = r4[2 * lane];
    float4 w1 = r4[2 * lane + 1];
    float s = w0.x * ha.x + w0.y * ha.y + w0.z * ha.z + w0.w * ha.w
            + w1.x * hb.x + w1.y * hb.y + w1.z * hb.z + w1.w * hb.w;
#pragma unroll
    for (int o = 16; o; o >>= 1) s += __shfl_xor_sync(0xFFFFFFFFu, s, o);
    return s;
}

__device__ __forceinline__ float rowdot(const __nv_bfloat16* __restrict__ row, int lane,
                                        float4 ha, float4 hb) {
    uint4 u = ((const uint4*)row)[lane];   // 8 bf16, cols 8*lane..8*lane+7
    float2 a = __bfloat1622float2(*(const __nv_bfloat162*)&u.x);
    float2 b = __bfloat1622float2(*(const __nv_bfloat162*)&u.y);
    float2 c = __bfloat1622float2(*(const __nv_bfloat162*)&u.z);
    float2 d = __bfloat1622float2(*(const __nv_bfloat162*)&u.w);
    float s = a.x * ha.x + a.y * ha.y + b.x * ha.z + b.y * ha.w
            + c.x * hb.x + c.y * hb.y + d.x * hb.z + d.y * hb.w;
#pragma unroll
    for (int o = 16; o; o >>= 1) s += __shfl_xor_sync(0xFFFFFFFFu, s, o);
    return s;
}

// ---------------------------------------------------------------------------
// Pre kernel: per-timestep f = elu(...), then Gx[t] = Wih_low[:, :256]@f + bih_low
// ---------------------------------------------------------------------------
__global__ void __launch_bounds__(256) pre_kernel(
    const float* __restrict__ v0, const float* __restrict__ m0,
    const float* __restrict__ W1v, const float* __restrict__ b1v,
    const float* __restrict__ W1m, const float* __restrict__ b1m,
    const float* __restrict__ Wih_low, const float* __restrict__ bih_low,
    float* __restrict__ Gx)
{
    int t = blockIdx.x;
    __shared__ float xv[768];
    __shared__ float f[256];
    int tid = threadIdx.x, lane = tid & 31, warp = tid >> 5;

    for (int i = tid; i < 768; i += 256) xv[i] = v0[t * 768 + i];
    __syncthreads();

    // f_v (128 outputs, 768-dot each): warp w owns rows [16w, 16w+16)
    for (int i = warp * 16; i < warp * 16 + 16; ++i) {
        float s = 0.f;
#pragma unroll 4
        for (int k = lane; k < 768; k += 32) s += W1v[i * 768 + k] * xv[k];
#pragma unroll
        for (int o = 16; o; o >>= 1) s += __shfl_xor_sync(0xFFFFFFFFu, s, o);
        if (lane == 0) f[i] = eluf(s + b1v[i]);
    }
    // f_m (128 outputs, 2-dot each)
    if (tid < 128) {
        float s = W1m[tid * 2 + 0] * m0[t * 2 + 0]
                + W1m[tid * 2 + 1] * m0[t * 2 + 1] + b1m[tid];
        f[128 + tid] = eluf(s);
    }
    __syncthreads();

    // Gx rows: 768 outputs of 256-dot
    for (int i = warp; i < 768; i += 8) {
        float s = 0.f;
#pragma unroll
        for (int k = lane; k < 256; k += 32) s += Wih_low[i * 512 + k] * f[k];
#pragma unroll
        for (int o = 16; o; o >>= 1) s += __shfl_xor_sync(0xFFFFFFFFu, s, o);
        if (lane == 0) Gx[t * 768 + i] = s + bih_low[i];
    }
}

// ---------------------------------------------------------------------------
// Scan kernel: one cluster of NCTA CTAs, 256 threads each. Each CTA owns
// S = 256/NCTA hidden indices j and keeps all 12 weight rows (4 matrices x 3
// gates) for them in shared memory. Per step:
//   phase A: gi_h2 = Wlh@h2, gh1 = Whl@h1, F = Whh2@h2 -> h1'   (sync)
//   phase B: gi2 = Wih2@h1' combined with stashed F    -> h2'   (sync)
// h1/h2 double-buffered in smem, broadcast to peers via st.shared::cluster.
// ---------------------------------------------------------------------------
template <int NCTA, typename WT>
__global__ void __launch_bounds__(256, 1) scan_kernel(
    const float* __restrict__ Wih_low,   // 768 x 512 (cols 256.. used here)
    const float* __restrict__ Whh_low,   // 768 x 256
    const float* __restrict__ bhh_low,
    const float* __restrict__ Wih_high,  // 768 x 256
    const float* __restrict__ Whh_high,  // 768 x 256
    const float* __restrict__ bih_high,
    const float* __restrict__ bhh_high,
    const float* __restrict__ Gx,        // TSTEPS x 768
    float* __restrict__ h1out)           // TSTEPS x 256
{
    constexpr int S  = 256 / NCTA;  // j's per CTA
    constexpr int SP = S / 8;       // j's per warp (8 warps)
    constexpr int WELEMS = 4 * 3 * S * 256;

    extern __shared__ unsigned char smraw[];
    WT* Wsm = (WT*)smraw;
    float* h1b = (float*)(smraw + (size_t)WELEMS * sizeof(WT));  // [2][256]
    float* h2b = h1b + 512;                                      // [2][256]

    const int tid = threadIdx.x, lane = tid & 31, warp = tid >> 5;
    const int cta = blockIdx.x;          // grid == one cluster
    const int jbase = cta * S;

    // ---- stage weight slice into smem (one-time) ----
    {
        const int N4 = WELEMS / 4;
        for (int i = tid; i < N4; i += 256) {
            int c4 = i & 63;             // float4 index within a 256-col row
            int rr = i >> 6;             // packed row 0..12*S-1
            int s  = rr % S;
            int g  = (rr / S) % 3;
            int m  = rr / (3 * S);
            int grow = g * 256 + jbase + s;
            const float* src;
            if (m == 0)      src = Wih_low  + (size_t)grow * 512 + 256 + c4 * 4;
            else if (m == 1) src = Whh_low  + (size_t)grow * 256 + c4 * 4;
            else if (m == 2) src = Wih_high + (size_t)grow * 256 + c4 * 4;
            else             src = Whh_high + (size_t)grow * 256 + c4 * 4;
            float4 v = *(const float4*)src;
            WT* dst = Wsm + (size_t)rr * 256 + c4 * 4;
            dst[0] = (WT)v.x; dst[1] = (WT)v.y; dst[2] = (WT)v.z; dst[3] = (WT)v.w;
        }
    }
    for (int i = tid; i < 512; i += 256) { h1b[i] = 0.f; h2b[i] = 0.f; }
    __syncthreads();
    cluster_sync_dev();   // all peers' h buffers init'd before any remote store

    // per-warp bias preload
    float bhl[SP][3], bi2[SP][3], bh2[SP][3];
    int js[SP];
#pragma unroll
    for (int p = 0; p < SP; p++) {
        int s = warp * SP + p;
        js[p] = jbase + s;
#pragma unroll
        for (int g = 0; g < 3; g++) {
            bhl[p][g] = bhh_low [g * 256 + js[p]];
            bi2[p][g] = bih_high[g * 256 + js[p]];
            bh2[p][g] = bhh_high[g * 256 + js[p]];
        }
    }

    for (int t = 0; t < TSTEPS; ++t) {
        const int cur = t & 1, nxt = cur ^ 1;
        const float* h1c = h1b + cur * 256;
        const float* h2c = h2b + cur * 256;

        float gx[SP][3];
#pragma unroll
        for (int p = 0; p < SP; p++)
#pragma unroll
            for (int g = 0; g < 3; g++)
                gx[p][g] = __ldg(Gx + t * 768 + g * 256 + js[p]);

        float4 h1a = ((const float4*)h1c)[2 * lane], h1v = ((const float4*)h1c)[2 * lane + 1];
        float4 h2a = ((const float4*)h2c)[2 * lane], h2v = ((const float4*)h2c)[2 * lane + 1];

        float F[SP][3], h1n[SP];
#pragma unroll
        for (int p = 0; p < SP; p++) {
            int s = warp * SP + p;
            float A0 = rowdot(Wsm + ((size_t)((0 * 3 + 0) * S + s)) * 256, lane, h2a, h2v);
            float A1 = rowdot(Wsm + ((size_t)((0 * 3 + 1) * S + s)) * 256, lane, h2a, h2v);
            float A2 = rowdot(Wsm + ((size_t)((0 * 3 + 2) * S + s)) * 256, lane, h2a, h2v);
            float B0 = rowdot(Wsm + ((size_t)((1 * 3 + 0) * S + s)) * 256, lane, h1a, h1v);
            float B1 = rowdot(Wsm + ((size_t)((1 * 3 + 1) * S + s)) * 256, lane, h1a, h1v);
            float B2 = rowdot(Wsm + ((size_t)((1 * 3 + 2) * S + s)) * 256, lane, h1a, h1v);
            F[p][0]  = rowdot(Wsm + ((size_t)((3 * 3 + 0) * S + s)) * 256, lane, h2a, h2v);
            F[p][1]  = rowdot(Wsm + ((size_t)((3 * 3 + 1) * S + s)) * 256, lane, h2a, h2v);
            F[p][2]  = rowdot(Wsm + ((size_t)((3 * 3 + 2) * S + s)) * 256, lane, h2a, h2v);
            float r = sigf(gx[p][0] + A0 + bhl[p][0] + B0);
            float z = sigf(gx[p][1] + A1 + bhl[p][1] + B1);
            float n = tanhf(gx[p][2] + A2 + r * (bhl[p][2] + B2));
            h1n[p] = (1.f - z) * n + z * h1c[js[p]];
        }
        // broadcast h1' slice to every CTA's next-buffer; also store scan output
#pragma unroll
        for (int p = 0; p < SP; p++) {
            if (lane >= p * NCTA && lane < (p + 1) * NCTA)
                st_remote_f32(h1b + nxt * 256 + js[p], lane - p * NCTA, h1n[p]);
            if (lane == p) h1out[t * 256 + js[p]] = h1n[p];
        }
        cluster_sync_dev();

        const float* h1nv = h1b + nxt * 256;
        float4 n1a = ((const float4*)h1nv)[2 * lane], n1v = ((const float4*)h1nv)[2 * lane + 1];
#pragma unroll
        for (int p = 0; p < SP; p++) {
            int s = warp * SP + p;
            float G0 = rowdot(Wsm + ((size_t)((2 * 3 + 0) * S + s)) * 256, lane, n1a, n1v);
            float G1 = rowdot(Wsm + ((size_t)((2 * 3 + 1) * S + s)) * 256, lane, n1a, n1v);
            float G2 = rowdot(Wsm + ((size_t)((2 * 3 + 2) * S + s)) * 256, lane, n1a, n1v);
            float r2 = sigf(G0 + bi2[p][0] + F[p][0] + bh2[p][0]);
            float z2 = sigf(G1 + bi2[p][1] + F[p][1] + bh2[p][1]);
            float n2 = tanhf(G2 + bi2[p][2] + r2 * (F[p][2] + bh2[p][2]));
            float h2n = (1.f - z2) * n2 + z2 * h2c[js[p]];
            if (lane >= p * NCTA && lane < (p + 1) * NCTA)
                st_remote_f32(h2b + nxt * 256 + js[p], lane - p * NCTA, h2n);
        }
        cluster_sync_dev();
    }
}

// ---------------------------------------------------------------------------
// Post kernel: v_n = sigmoid(W2v @ elu(h1[:128])), m_n = tanh(W2m @ elu(h1[128:]))
// ---------------------------------------------------------------------------
__global__ void __launch_bounds__(256) post_kernel(
    const float* __restrict__ h1out,
    const float* __restrict__ W2v, const float* __restrict__ b2v,
    const float* __restrict__ W2m, const float* __restrict__ b2m,
    float* __restrict__ out)
{
    int t = blockIdx.x;
    __shared__ float fe[256];
    int tid = threadIdx.x, lane = tid & 31, warp = tid >> 5;

    fe[tid] = eluf(h1out[t * 256 + tid]);
    __syncthreads();

    float* vout = out;                    // TSTEPS*768
    float* mout = out + TSTEPS * 768;     // TSTEPS*2

    for (int i = warp; i < 768; i += 8) {
        float s = 0.f;
#pragma unroll
        for (int k = lane; k < 128; k += 32) s += W2v[i * 128 + k] * fe[k];
#pragma unroll
        for (int o = 16; o; o >>= 1) s += __shfl_xor_sync(0xFFFFFFFFu, s, o);
        if (lane == 0) vout[t * 768 + i] = sigf(s + b2v[i]);
    }
    if (warp < 2) {
        int i = warp;
        float s = 0.f;
#pragma unroll
        for (int k = lane; k < 128; k += 32) s += W2m[i * 128 + k] * fe[128 + k];
#pragma unroll
        for (int o = 16; o; o >>= 1) s += __shfl_xor_sync(0xFFFFFFFFu, s, o);
        if (lane == 0) mout[t * 2 + i] = tanhf(s + b2m[i]);
    }
}

// ---------------------------------------------------------------------------
extern "C" void kernel_launch(void* const* d_in, const int* in_sizes, int n_in,
                              void* d_out, int out_size)
{
    const float* v0       = (const float*)d_in[0];
    const float* m0       = (const float*)d_in[1];
    const float* W1v      = (const float*)d_in[2];
    const float* b1v      = (const float*)d_in[3];
    const float* W1m      = (const float*)d_in[4];
    const float* b1m      = (const float*)d_in[5];
    const float* Wih_low  = (const float*)d_in[6];
    const float* Whh_low  = (const float*)d_in[7];
    const float* bih_low  = (const float*)d_in[8];
    const float* bhh_low  = (const float*)d_in[9];
    const float* Wih_high = (const float*)d_in[10];
    const float* Whh_high = (const float*)d_in[11];
    const float* bih_high = (const float*)d_in[12];
    const float* bhh_high = (const float*)d_in[13];
    const float* W2v      = (const float*)d_in[14];
    const float* b2v      = (const float*)d_in[15];
    const float* W2m      = (const float*)d_in[16];
    const float* b2m      = (const float*)d_in[17];
    float* out = (float*)d_out;

    float *Gx = nullptr, *h1s = nullptr;
    cudaGetSymbolAddress((void**)&Gx, g_Gx);
    cudaGetSymbolAddress((void**)&h1s, g_h1);

    pre_kernel<<<TSTEPS, 256>>>(v0, m0, W1v, b1v, W1m, b1m, Wih_low, bih_low, Gx);

    // ---- scan: prefer 16-CTA fp32 cluster; fall back to portable 8-CTA bf16 ----
    constexpr size_t SMEM16 = (size_t)4 * 3 * 16 * 256 * sizeof(float) + 4 * 512 * sizeof(float) / 2 + 2048;
    // (explicit: 196608 weight bytes + 4096 h-buffer bytes)
    const size_t smem16 = 196608 + 4096;
    const size_t smem8  = (size_t)4 * 3 * 32 * 256 * sizeof(__nv_bfloat16) + 4096;  // 196608+4096
    (void)SMEM16;

    auto k16 = scan_kernel<16, float>;
    auto k8  = scan_kernel<8, __nv_bfloat16>;

    cudaFuncSetAttribute(k16, cudaFuncAttributeMaxDynamicSharedMemorySize, (int)smem16);
    cudaError_t eNp = cudaFuncSetAttribute(k16, cudaFuncAttributeNonPortableClusterSizeAllowed, 1);

    cudaLaunchConfig_t cfg = {};
    cfg.blockDim = {256, 1, 1};
    cfg.stream = 0;

    int maxC = 0;
    if (eNp == cudaSuccess) {
        cfg.gridDim = {16, 1, 1};
        cfg.dynamicSmemBytes = smem16;
        cudaError_t eq = cudaOccupancyMaxPotentialClusterSize(&maxC, k16, &cfg);
        if (eq != cudaSuccess) maxC = 0;
    }

    cudaLaunchAttribute at[1];
    at[0].id = cudaLaunchAttributeClusterDimension;

    if (maxC >= 16) {
        cfg.gridDim = {16, 1, 1};
        cfg.dynamicSmemBytes = smem16;
        at[0].val.clusterDim = {16, 1, 1};
        cfg.attrs = at; cfg.numAttrs = 1;
        cudaLaunchKernelEx(&cfg, k16, Wih_low, Whh_low, bhh_low,
                           Wih_high, Whh_high, bih_high, bhh_high,
                           (const float*)Gx, h1s);
    } else {
        cudaFuncSetAttribute(k8, cudaFuncAttributeMaxDynamicSharedMemorySize, (int)smem8);
        cfg.gridDim = {8, 1, 1};
        cfg.dynamicSmemBytes = smem8;
        at[0].val.clusterDim = {8, 1, 1};
        cfg.attrs = at; cfg.numAttrs = 1;
        cudaLaunchKernelEx(&cfg, k8, Wih_low, Whh_low, bhh_low,
                           Wih_high, Whh_high, bih_high, bhh_high,
                           (const float*)Gx, h1s);
    }

    post_kernel<<<TSTEPS, 256>>>(h1s, W2v, b2v, W2m, b2m, out);
}

// round 3
// speedup vs baseline: 1.4501x; 1.4501x over previous
#include <cuda_runtime.h>
#include <cuda_bf16.h>
#include <cstdint>

// ---------------------------------------------------------------------------
// Model: T=50, B=1. VIN=768, VF=128, MIN=2, MF=128, H=256.
//  pre:  f = elu([W1v@v ; W1m@m]) ; Gx[t] = Wih_low[:, :256] @ f[t] + bih_low
//  scan: h1 = GRU([f;h2], h1) with (Wih_low split), h2 = GRU(h1, h2)
//  post: v_n = sigmoid(W2v @ elu(h1[:128])), m_n = tanh(W2m @ elu(h1[128:256]))
// ---------------------------------------------------------------------------

#define TSTEPS 50
#define HSZ    256

__device__ float g_Gx[TSTEPS * 768];   // precomputed input gates for low GRU
__device__ float g_h1[TSTEPS * HSZ];   // h1 per step (scan output)
__device__ float g_f [TSTEPS * HSZ];   // elu features per step

__device__ __forceinline__ float eluf(float x) { return x > 0.f ? x : expm1f(x); }
__device__ __forceinline__ float sigf(float x) { return 1.f / (1.f + expf(-x)); }

__device__ __forceinline__ void cluster_sync_dev() {
    asm volatile("barrier.cluster.arrive.aligned;\n\t"
                 "barrier.cluster.wait.aligned;" ::: "memory");
}

__device__ __forceinline__ uint32_t mapa_sh(uint32_t a, int rank) {
    uint32_t ra;
    asm volatile("mapa.shared::cluster.u32 %0, %1, %2;" : "=r"(ra) : "r"(a), "r"(rank));
    return ra;
}

// Remote smem store with mbarrier transaction-count completion (4 bytes).
__device__ __forceinline__ void st_async_b32(uint32_t r_addr, uint32_t r_mbar, float v) {
    asm volatile("st.async.shared::cluster.mbarrier::complete_tx::bytes.b32 [%0], %1, [%2];"
                 :: "r"(r_addr), "r"(__float_as_uint(v)), "r"(r_mbar) : "memory");
}

__device__ __forceinline__ void mbar_init(uint32_t mbar, uint32_t cnt) {
    asm volatile("mbarrier.init.shared.b64 [%0], %1;" :: "r"(mbar), "r"(cnt) : "memory");
}
__device__ __forceinline__ void mbar_expect_tx(uint32_t mbar, uint32_t bytes) {
    asm volatile("mbarrier.arrive.expect_tx.shared.b64 _, [%0], %1;"
                 :: "r"(mbar), "r"(bytes) : "memory");
}
__device__ __forceinline__ void mbar_wait_cluster(uint32_t mbar, uint32_t parity) {
    asm volatile(
        "{\n\t"
        ".reg .pred P;\n\t"
        "WL_%=:\n\t"
        "mbarrier.try_wait.parity.acquire.cluster.shared::cta.b64 P, [%0], %1, 0x989680;\n\t"
        "@P bra WD_%=;\n\t"
        "bra WL_%=;\n\t"
        "WD_%=:\n\t"
        "}" :: "r"(mbar), "r"(parity) : "memory");
}

// 256-wide dot of one weight row (smem) against h (in regs: cols 8*lane..8*lane+7).
__device__ __forceinline__ float rowdot(const float* __restrict__ row, int lane,
                                        float4 ha, float4 hb) {
    const float4* r4 = (const float4*)row;
    float4 w0 = r4[2 * lane];
    float4 w1 = r4[2 * lane + 1];
    float s = w0.x * ha.x + w0.y * ha.y + w0.z * ha.z + w0.w * ha.w
            + w1.x * hb.x + w1.y * hb.y + w1.z * hb.z + w1.w * hb.w;
#pragma unroll
    for (int o = 16; o; o >>= 1) s += __shfl_xor_sync(0xFFFFFFFFu, s, o);
    return s;
}

__device__ __forceinline__ float rowdot(const __nv_bfloat16* __restrict__ row, int lane,
                                        float4 ha, float4 hb) {
    uint4 u = ((const uint4*)row)[lane];   // 8 bf16, cols 8*lane..8*lane+7
    float2 a = __bfloat1622float2(*(const __nv_bfloat162*)&u.x);
    float2 b = __bfloat1622float2(*(const __nv_bfloat162*)&u.y);
    float2 c = __bfloat1622float2(*(const __nv_bfloat162*)&u.z);
    float2 d = __bfloat1622float2(*(const __nv_bfloat162*)&u.w);
    float s = a.x * ha.x + a.y * ha.y + b.x * ha.z + b.y * ha.w
            + c.x * hb.x + c.y * hb.y + d.x * hb.z + d.y * hb.w;
#pragma unroll
    for (int o = 16; o; o >>= 1) s += __shfl_xor_sync(0xFFFFFFFFu, s, o);
    return s;
}

// ---------------------------------------------------------------------------
// f kernel: f[t] = elu([W1v@v ; W1m@m]).  grid (2, TSTEPS) x 256 threads.
// block x owns f_v rows [64x, 64x+64); block x==1 also does the f_m rows.
// ---------------------------------------------------------------------------
__global__ void __launch_bounds__(256) f_kernel(
    const float* __restrict__ v0, const float* __restrict__ m0,
    const float* __restrict__ W1v, const float* __restrict__ b1v,
    const float* __restrict__ W1m, const float* __restrict__ b1m,
    float* __restrict__ f)
{
    int t = blockIdx.y;
    __shared__ float xv[768];
    int tid = threadIdx.x, lane = tid & 31, warp = tid >> 5;

    for (int i = tid; i < 768; i += 256) xv[i] = v0[t * 768 + i];
    __syncthreads();

    int r0 = blockIdx.x * 64 + warp * 8;
#pragma unroll
    for (int i = r0; i < r0 + 8; ++i) {
        float s = 0.f;
#pragma unroll 4
        for (int k = lane; k < 768; k += 32) s += W1v[i * 768 + k] * xv[k];
#pragma unroll
        for (int o = 16; o; o >>= 1) s += __shfl_xor_sync(0xFFFFFFFFu, s, o);
        if (lane == 0) f[t * 256 + i] = eluf(s + b1v[i]);
    }
    if (blockIdx.x == 1 && tid < 128) {
        float s = W1m[tid * 2 + 0] * m0[t * 2 + 0]
                + W1m[tid * 2 + 1] * m0[t * 2 + 1] + b1m[tid];
        f[t * 256 + 128 + tid] = eluf(s);
    }
}

// ---------------------------------------------------------------------------
// Gx kernel: Gx[t] = Wih_low[:, :256] @ f[t] + bih_low.  grid (6, TSTEPS).
// block x owns rows [128x, 128x+128); warp owns 16 rows.
// ---------------------------------------------------------------------------
__global__ void __launch_bounds__(256) gx_kernel(
    const float* __restrict__ Wih_low, const float* __restrict__ bih_low,
    const float* __restrict__ f, float* __restrict__ Gx)
{
    int t = blockIdx.y;
    __shared__ float fs[256];
    int tid = threadIdx.x, lane = tid & 31, warp = tid >> 5;

    fs[tid] = f[t * 256 + tid];
    __syncthreads();

    int r0 = blockIdx.x * 128 + warp * 16;
#pragma unroll
    for (int i = r0; i < r0 + 16; ++i) {
        float s = 0.f;
#pragma unroll
        for (int k = lane; k < 256; k += 32) s += Wih_low[i * 512 + k] * fs[k];
#pragma unroll
        for (int o = 16; o; o >>= 1) s += __shfl_xor_sync(0xFFFFFFFFu, s, o);
        if (lane == 0) Gx[t * 768 + i] = s + bih_low[i];
    }
}

// ---------------------------------------------------------------------------
// Scan kernel: one cluster of NCTA CTAs, 256 threads each. Each CTA owns
// S = 256/NCTA hidden indices j and keeps all 12 weight rows (4 matrices x 3
// gates) for them in shared memory. Per step:
//   phase A: gi_h2 = Wlh@h2, gh1 = Whl@h1, F = Whh2@h2 -> h1'   (mbar1)
//   phase B: gi2 = Wih2@h1' combined with stashed F    -> h2'   (mbar2)
// h1/h2 double-buffered; broadcast via st.async w/ mbarrier complete_tx:
// each CTA expects 256 floats = 1024 tx bytes per phase. No cluster barrier
// in the loop. Safety of buffer reuse: phase X(t+1) stores can only begin
// after the writer passed the phase (t) waits, which require ALL CTAs' phase
// (t) stores, which program-order-follow each warp's phase (t) reads.
// ---------------------------------------------------------------------------
template <int NCTA, typename WT>
__global__ void __launch_bounds__(256, 1) scan_kernel(
    const float* __restrict__ Wih_low,   // 768 x 512 (cols 256.. used here)
    const float* __restrict__ Whh_low,   // 768 x 256
    const float* __restrict__ bhh_low,
    const float* __restrict__ Wih_high,  // 768 x 256
    const float* __restrict__ Whh_high,  // 768 x 256
    const float* __restrict__ bih_high,
    const float* __restrict__ bhh_high,
    const float* __restrict__ Gx,        // TSTEPS x 768
    float* __restrict__ h1out)           // TSTEPS x 256
{
    constexpr int S  = 256 / NCTA;  // j's per CTA
    constexpr int SP = S / 8;       // j's per warp (8 warps)
    constexpr int WELEMS = 4 * 3 * S * 256;
    constexpr uint32_t TXB = 256 * 4;   // bytes received per phase

    extern __shared__ unsigned char smraw[];
    WT* Wsm = (WT*)smraw;
    float* h1b = (float*)(smraw + (size_t)WELEMS * sizeof(WT));  // [2][256]
    float* h2b = h1b + 512;                                      // [2][256]
    unsigned long long* mbars = (unsigned long long*)(h2b + 512);  // [2]

    const int tid = threadIdx.x, lane = tid & 31, warp = tid >> 5;
    const int cta = blockIdx.x;          // grid == one cluster
    const int jbase = cta * S;

    const uint32_t mb1 = (uint32_t)__cvta_generic_to_shared(mbars + 0);
    const uint32_t mb2 = (uint32_t)__cvta_generic_to_shared(mbars + 1);
    const uint32_t h1sm = (uint32_t)__cvta_generic_to_shared(h1b);
    const uint32_t h2sm = (uint32_t)__cvta_generic_to_shared(h2b);

    if (tid == 0) { mbar_init(mb1, 1); mbar_init(mb2, 1); }

    // ---- stage weight slice into smem (one-time) ----
    {
        const int N4 = WELEMS / 4;
        for (int i = tid; i < N4; i += 256) {
            int c4 = i & 63;             // float4 index within a 256-col row
            int rr = i >> 6;             // packed row 0..12*S-1
            int s  = rr % S;
            int g  = (rr / S) % 3;
            int m  = rr / (3 * S);
            int grow = g * 256 + jbase + s;
            const float* src;
            if (m == 0)      src = Wih_low  + (size_t)grow * 512 + 256 + c4 * 4;
            else if (m == 1) src = Whh_low  + (size_t)grow * 256 + c4 * 4;
            else if (m == 2) src = Wih_high + (size_t)grow * 256 + c4 * 4;
            else             src = Whh_high + (size_t)grow * 256 + c4 * 4;
            float4 v = *(const float4*)src;
            WT* dst = Wsm + (size_t)rr * 256 + c4 * 4;
            dst[0] = (WT)v.x; dst[1] = (WT)v.y; dst[2] = (WT)v.z; dst[3] = (WT)v.w;
        }
    }
    for (int i = tid; i < 512; i += 256) { h1b[i] = 0.f; h2b[i] = 0.f; }
    __syncthreads();
    cluster_sync_dev();   // peers' h buffers + mbarriers ready before remote stores

    // per-warp bias preload
    float bhl[SP][3], bi2[SP][3], bh2[SP][3];
    int js[SP];
#pragma unroll
    for (int p = 0; p < SP; p++) {
        int s = warp * SP + p;
        js[p] = jbase + s;
#pragma unroll
        for (int g = 0; g < 3; g++) {
            bhl[p][g] = bhh_low [g * 256 + js[p]];
            bi2[p][g] = bih_high[g * 256 + js[p]];
            bh2[p][g] = bhh_high[g * 256 + js[p]];
        }
    }

    for (int t = 0; t < TSTEPS; ++t) {
        const int cur = t & 1, nxt = cur ^ 1;
        const uint32_t par = (uint32_t)(t & 1);
        if (tid == 0) { mbar_expect_tx(mb1, TXB); mbar_expect_tx(mb2, TXB); }

        const float* h1c = h1b + cur * 256;
        const float* h2c = h2b + cur * 256;

        float gx[SP][3];
#pragma unroll
        for (int p = 0; p < SP; p++)
#pragma unroll
            for (int g = 0; g < 3; g++)
                gx[p][g] = __ldg(Gx + t * 768 + g * 256 + js[p]);

        float4 h1a = ((const float4*)h1c)[2 * lane], h1v = ((const float4*)h1c)[2 * lane + 1];
        float4 h2a = ((const float4*)h2c)[2 * lane], h2v = ((const float4*)h2c)[2 * lane + 1];

        float F[SP][3], h1n[SP];
#pragma unroll
        for (int p = 0; p < SP; p++) {
            int s = warp * SP + p;
            float A0 = rowdot(Wsm + ((size_t)((0 * 3 + 0) * S + s)) * 256, lane, h2a, h2v);
            float A1 = rowdot(Wsm + ((size_t)((0 * 3 + 1) * S + s)) * 256, lane, h2a, h2v);
            float A2 = rowdot(Wsm + ((size_t)((0 * 3 + 2) * S + s)) * 256, lane, h2a, h2v);
            float B0 = rowdot(Wsm + ((size_t)((1 * 3 + 0) * S + s)) * 256, lane, h1a, h1v);
            float B1 = rowdot(Wsm + ((size_t)((1 * 3 + 1) * S + s)) * 256, lane, h1a, h1v);
            float B2 = rowdot(Wsm + ((size_t)((1 * 3 + 2) * S + s)) * 256, lane, h1a, h1v);
            F[p][0]  = rowdot(Wsm + ((size_t)((3 * 3 + 0) * S + s)) * 256, lane, h2a, h2v);
            F[p][1]  = rowdot(Wsm + ((size_t)((3 * 3 + 1) * S + s)) * 256, lane, h2a, h2v);
            F[p][2]  = rowdot(Wsm + ((size_t)((3 * 3 + 2) * S + s)) * 256, lane, h2a, h2v);
            float r = sigf(gx[p][0] + A0 + bhl[p][0] + B0);
            float z = sigf(gx[p][1] + A1 + bhl[p][1] + B1);
            float n = tanhf(gx[p][2] + A2 + r * (bhl[p][2] + B2));
            h1n[p] = (1.f - z) * n + z * h1c[js[p]];
        }
        // broadcast h1' slice to every CTA's next-buffer (st.async + tx count)
#pragma unroll
        for (int p = 0; p < SP; p++) {
            if (lane >= p * NCTA && lane < (p + 1) * NCTA) {
                int rank = lane - p * NCTA;
                uint32_t slot = h1sm + (uint32_t)(nxt * 256 + js[p]) * 4u;
                st_async_b32(mapa_sh(slot, rank), mapa_sh(mb1, rank), h1n[p]);
            }
            if (lane == p) h1out[t * 256 + js[p]] = h1n[p];
        }
        mbar_wait_cluster(mb1, par);

        const float* h1nv = h1b + nxt * 256;
        float4 n1a = ((const float4*)h1nv)[2 * lane], n1v = ((const float4*)h1nv)[2 * lane + 1];
#pragma unroll
        for (int p = 0; p < SP; p++) {
            int s = warp * SP + p;
            float G0 = rowdot(Wsm + ((size_t)((2 * 3 + 0) * S + s)) * 256, lane, n1a, n1v);
            float G1 = rowdot(Wsm + ((size_t)((2 * 3 + 1) * S + s)) * 256, lane, n1a, n1v);
            float G2 = rowdot(Wsm + ((size_t)((2 * 3 + 2) * S + s)) * 256, lane, n1a, n1v);
            float r2 = sigf(G0 + bi2[p][0] + F[p][0] + bh2[p][0]);
            float z2 = sigf(G1 + bi2[p][1] + F[p][1] + bh2[p][1]);
            float n2 = tanhf(G2 + bi2[p][2] + r2 * (F[p][2] + bh2[p][2]));
            float h2n = (1.f - z2) * n2 + z2 * h2c[js[p]];
            if (lane >= p * NCTA && lane < (p + 1) * NCTA) {
                int rank = lane - p * NCTA;
                uint32_t slot = h2sm + (uint32_t)(nxt * 256 + js[p]) * 4u;
                st_async_b32(mapa_sh(slot, rank), mapa_sh(mb2, rank), h2n);
            }
        }
        mbar_wait_cluster(mb2, par);
    }
    cluster_sync_dev();   // drain before any CTA exits
}

// ---------------------------------------------------------------------------
// Post kernel: v_n = sigmoid(W2v @ elu(h1[:128])), m_n = tanh(W2m @ elu(h1[128:]))
// grid (4, TSTEPS): block x owns v rows [192x, 192x+192); warp owns 24 rows.
// block x==0 additionally computes the 2 m rows (warps 0 and 1).
// ---------------------------------------------------------------------------
__global__ void __launch_bounds__(256) post_kernel(
    const float* __restrict__ h1out,
    const float* __restrict__ W2v, const float* __restrict__ b2v,
    const float* __restrict__ W2m, const float* __restrict__ b2m,
    float* __restrict__ out)
{
    int t = blockIdx.y;
    __shared__ float fe[256];
    int tid = threadIdx.x, lane = tid & 31, warp = tid >> 5;

    fe[tid] = eluf(h1out[t * 256 + tid]);
    __syncthreads();

    float* vout = out;                    // TSTEPS*768
    float* mout = out + TSTEPS * 768;     // TSTEPS*2

    int r0 = blockIdx.x * 192 + warp * 24;
#pragma unroll
    for (int i = r0; i < r0 + 24; ++i) {
        float s = 0.f;
#pragma unroll
        for (int k = lane; k < 128; k += 32) s += W2v[i * 128 + k] * fe[k];
#pragma unroll
        for (int o = 16; o; o >>= 1) s += __shfl_xor_sync(0xFFFFFFFFu, s, o);
        if (lane == 0) vout[t * 768 + i] = sigf(s + b2v[i]);
    }
    if (blockIdx.x == 0 && warp < 2) {
        int i = warp;
        float s = 0.f;
#pragma unroll
        for (int k = lane; k < 128; k += 32) s += W2m[i * 128 + k] * fe[128 + k];
#pragma unroll
        for (int o = 16; o; o >>= 1) s += __shfl_xor_sync(0xFFFFFFFFu, s, o);
        if (lane == 0) mout[t * 2 + i] = tanhf(s + b2m[i]);
    }
}

// ---------------------------------------------------------------------------
extern "C" void kernel_launch(void* const* d_in, const int* in_sizes, int n_in,
                              void* d_out, int out_size)
{
    const float* v0       = (const float*)d_in[0];
    const float* m0       = (const float*)d_in[1];
    const float* W1v      = (const float*)d_in[2];
    const float* b1v      = (const float*)d_in[3];
    const float* W1m      = (const float*)d_in[4];
    const float* b1m      = (const float*)d_in[5];
    const float* Wih_low  = (const float*)d_in[6];
    const float* Whh_low  = (const float*)d_in[7];
    const float* bih_low  = (const float*)d_in[8];
    const float* bhh_low  = (const float*)d_in[9];
    const float* Wih_high = (const float*)d_in[10];
    const float* Whh_high = (const float*)d_in[11];
    const float* bih_high = (const float*)d_in[12];
    const float* bhh_high = (const float*)d_in[13];
    const float* W2v      = (const float*)d_in[14];
    const float* b2v      = (const float*)d_in[15];
    const float* W2m      = (const float*)d_in[16];
    const float* b2m      = (const float*)d_in[17];
    float* out = (float*)d_out;

    float *Gx = nullptr, *h1s = nullptr, *fbuf = nullptr;
    cudaGetSymbolAddress((void**)&Gx, g_Gx);
    cudaGetSymbolAddress((void**)&h1s, g_h1);
    cudaGetSymbolAddress((void**)&fbuf, g_f);

    f_kernel <<<dim3(2, TSTEPS), 256>>>(v0, m0, W1v, b1v, W1m, b1m, fbuf);
    gx_kernel<<<dim3(6, TSTEPS), 256>>>(Wih_low, bih_low, fbuf, Gx);

    // ---- scan: prefer 16-CTA fp32 cluster; fall back to portable 8-CTA bf16 ----
    const size_t smem16 = 196608 + 4096 + 64;   // weights + h buffers + mbarriers
    const size_t smem8  = 196608 + 4096 + 64;

    auto k16 = scan_kernel<16, float>;
    auto k8  = scan_kernel<8, __nv_bfloat16>;

    cudaFuncSetAttribute(k16, cudaFuncAttributeMaxDynamicSharedMemorySize, (int)smem16);
    cudaError_t eNp = cudaFuncSetAttribute(k16, cudaFuncAttributeNonPortableClusterSizeAllowed, 1);

    cudaLaunchConfig_t cfg = {};
    cfg.blockDim = {256, 1, 1};
    cfg.stream = 0;

    int maxC = 0;
    if (eNp == cudaSuccess) {
        cfg.gridDim = {16, 1, 1};
        cfg.dynamicSmemBytes = smem16;
        cudaError_t eq = cudaOccupancyMaxPotentialClusterSize(&maxC, k16, &cfg);
        if (eq != cudaSuccess) maxC = 0;
    }

    cudaLaunchAttribute at[1];
    at[0].id = cudaLaunchAttributeClusterDimension;

    if (maxC >= 16) {
        cfg.gridDim = {16, 1, 1};
        cfg.dynamicSmemBytes = smem16;
        at[0].val.clusterDim = {16, 1, 1};
        cfg.attrs = at; cfg.numAttrs = 1;
        cudaLaunchKernelEx(&cfg, k16, Wih_low, Whh_low, bhh_low,
                           Wih_high, Whh_high, bih_high, bhh_high,
                           (const float*)Gx, h1s);
    } else {
        cudaFuncSetAttribute(k8, cudaFuncAttributeMaxDynamicSharedMemorySize, (int)smem8);
        cfg.gridDim = {8, 1, 1};
        cfg.dynamicSmemBytes = smem8;
        at[0].val.clusterDim = {8, 1, 1};
        cfg.attrs = at; cfg.numAttrs = 1;
        cudaLaunchKernelEx(&cfg, k8, Wih_low, Whh_low, bhh_low,
                           Wih_high, Whh_high, bih_high, bhh_high,
                           (const float*)Gx, h1s);
    }

    post_kernel<<<dim3(4, TSTEPS), 256>>>(h1s, W2v, b2v, W2m, b2m, out);
}

// round 7
// speedup vs baseline: 2.1801x; 1.5034x over previous
#include <cuda_runtime.h>
#include <cuda_bf16.h>
#include <cstdint>

// ---------------------------------------------------------------------------
// Model: T=50, B=1. VIN=768, VF=128, MIN=2, MF=128, H=256.
//  pre:  f = elu([W1v@v ; W1m@m]) ; Gx[t] = Wih_low[:, :256] @ f[t] + bih_low
//  scan: h1 = GRU([f;h2], h1) (Wih_low split), h2 = GRU(h1, h2)
//  post: v_n = sigmoid(W2v @ elu(h1[:128])), m_n = tanh(W2m @ elu(h1[128:256]))
// ---------------------------------------------------------------------------

#define TSTEPS 50
#define HSZ    256

__device__ float g_Gx[TSTEPS * 768];
__device__ float g_h1[TSTEPS * HSZ];
__device__ float g_f [TSTEPS * HSZ];

__device__ __forceinline__ float eluf(float x) { return x > 0.f ? x : expm1f(x); }
__device__ __forceinline__ float sigf(float x) { return 1.f / (1.f + expf(-x)); }

__device__ __forceinline__ void cluster_sync_dev() {
    asm volatile("barrier.cluster.arrive.aligned;\n\t"
                 "barrier.cluster.wait.aligned;" ::: "memory");
}

__device__ __forceinline__ uint32_t mapa_sh(uint32_t a, int rank) {
    uint32_t ra;
    asm volatile("mapa.shared::cluster.u32 %0, %1, %2;" : "=r"(ra) : "r"(a), "r"(rank));
    return ra;
}

__device__ __forceinline__ void st_async_b32(uint32_t r_addr, uint32_t r_mbar, float v) {
    asm volatile("st.async.shared::cluster.mbarrier::complete_tx::bytes.b32 [%0], %1, [%2];"
                 :: "r"(r_addr), "r"(__float_as_uint(v)), "r"(r_mbar) : "memory");
}

__device__ __forceinline__ void mbar_init(uint32_t mbar, uint32_t cnt) {
    asm volatile("mbarrier.init.shared.b64 [%0], %1;" :: "r"(mbar), "r"(cnt) : "memory");
}
__device__ __forceinline__ void mbar_expect_tx(uint32_t mbar, uint32_t bytes) {
    asm volatile("mbarrier.arrive.expect_tx.shared.b64 _, [%0], %1;"
                 :: "r"(mbar), "r"(bytes) : "memory");
}
__device__ __forceinline__ void mbar_wait_cluster(uint32_t mbar, uint32_t parity) {
    asm volatile(
        "{\n\t"
        ".reg .pred P;\n\t"
        "WL_%=:\n\t"
        "mbarrier.try_wait.parity.acquire.cluster.shared::cta.b64 P, [%0], %1, 0x989680;\n\t"
        "@P bra WD_%=;\n\t"
        "bra WL_%=;\n\t"
        "WD_%=:\n\t"
        "}" :: "r"(mbar), "r"(parity) : "memory");
}

// ---------------------------------------------------------------------------
// f kernel: f[t] = elu([W1v@v ; W1m@m]).  grid (2, TSTEPS) x 256.
// ---------------------------------------------------------------------------
__global__ void __launch_bounds__(256) f_kernel(
    const float* __restrict__ v0, const float* __restrict__ m0,
    const float* __restrict__ W1v, const float* __restrict__ b1v,
    const float* __restrict__ W1m, const float* __restrict__ b1m,
    float* __restrict__ f)
{
    int t = blockIdx.y;
    __shared__ float xv[768];
    int tid = threadIdx.x, lane = tid & 31, warp = tid >> 5;

    for (int i = tid; i < 768; i += 256) xv[i] = v0[t * 768 + i];
    __syncthreads();

    int r0 = blockIdx.x * 64 + warp * 8;
#pragma unroll
    for (int i = r0; i < r0 + 8; ++i) {
        float s = 0.f;
#pragma unroll 4
        for (int k = lane; k < 768; k += 32) s += W1v[i * 768 + k] * xv[k];
#pragma unroll
        for (int o = 16; o; o >>= 1) s += __shfl_xor_sync(0xFFFFFFFFu, s, o);
        if (lane == 0) f[t * 256 + i] = eluf(s + b1v[i]);
    }
    if (blockIdx.x == 1 && tid < 128) {
        float s = W1m[tid * 2 + 0] * m0[t * 2 + 0]
                + W1m[tid * 2 + 1] * m0[t * 2 + 1] + b1m[tid];
        f[t * 256 + 128 + tid] = eluf(s);
    }
}

// ---------------------------------------------------------------------------
// Gx kernel: Gx[t] = Wih_low[:, :256] @ f[t] + bih_low.  grid (6, TSTEPS).
// ---------------------------------------------------------------------------
__global__ void __launch_bounds__(256) gx_kernel(
    const float* __restrict__ Wih_low, const float* __restrict__ bih_low,
    const float* __restrict__ f, float* __restrict__ Gx)
{
    int t = blockIdx.y;
    __shared__ float fs[256];
    int tid = threadIdx.x, lane = tid & 31, warp = tid >> 5;

    fs[tid] = f[t * 256 + tid];
    __syncthreads();

    int r0 = blockIdx.x * 128 + warp * 16;
#pragma unroll
    for (int i = r0; i < r0 + 16; ++i) {
        float s = 0.f;
#pragma unroll
        for (int k = lane; k < 256; k += 32) s += Wih_low[i * 512 + k] * fs[k];
#pragma unroll
        for (int o = 16; o; o >>= 1) s += __shfl_xor_sync(0xFFFFFFFFu, s, o);
        if (lane == 0) Gx[t * 768 + i] = s + bih_low[i];
    }
}

// ---------------------------------------------------------------------------
// Scan kernel, 16-CTA cluster, 256 threads. Each CTA owns 16 j's; each warp
// owns 2 j's (j0 = jbase + warp*2, j1 = j0+1).
// Quad-pass GEMV: warp = 4 groups of 8 lanes; each pass computes 4 rows;
// lane (grp,sub) covers k-chunks {4*(m*8+sub)..+4} for m=0..7 (conflict-free
// LDS.128), reduce = 3 shfl_xor within the 8-lane group.
// Row layout in smem (per warp, 24 rows in pass order) — NOTE pairing:
//   phase A quad k (k=0..2): {Whh_low[k,j0],   Wih_low_h2[k,j0],
//                             Whh_low[k,j1],   Wih_low_h2[k,j1]}
//   phase B quad k:          {Wih_high[k,j0],  Whh_high[k,j0],
//                             Wih_high[k,j1],  Whh_high[k,j1]}
// Operand per group: EVEN groups -> h1c (A) / h1n (B, reload);
//                    ODD  groups -> h2c (A) / h2c (B, KEPT in regs).
// Gate combine via shfl from the 2 groups of each j; the 16 lanes of each j
// then broadcast h1n/h2n to the 16 CTAs via st.async (1 store/lane).
// ---------------------------------------------------------------------------
__global__ void __launch_bounds__(256, 1) scan16_kernel(
    const float* __restrict__ Wih_low,   // 768 x 512
    const float* __restrict__ Whh_low,   // 768 x 256
    const float* __restrict__ bhh_low,
    const float* __restrict__ Wih_high,  // 768 x 256
    const float* __restrict__ Whh_high,  // 768 x 256
    const float* __restrict__ bih_high,
    const float* __restrict__ bhh_high,
    const float* __restrict__ Gx,        // TSTEPS x 768
    float* __restrict__ h1out)           // TSTEPS x 256
{
    constexpr uint32_t TXB = 256 * 4;

    extern __shared__ unsigned char smraw[];
    float* Wsm = (float*)smraw;              // 192 rows x 256 floats
    float* h1b = Wsm + 192 * 256;            // [2][256]
    float* h2b = h1b + 512;                  // [2][256]
    float* gxs = h2b + 512;                  // [TSTEPS][48]  (3 gates x 16 j)
    unsigned long long* mbars = (unsigned long long*)(gxs + TSTEPS * 48);

    const int tid = threadIdx.x, lane = tid & 31, warp = tid >> 5;
    const int sub = lane & 7, grp = (lane >> 3) & 3;
    const int cta = blockIdx.x;
    const int jbase = cta * 16;

    const uint32_t mb1 = (uint32_t)__cvta_generic_to_shared(mbars + 0);
    const uint32_t mb2 = (uint32_t)__cvta_generic_to_shared(mbars + 1);
    const uint32_t h1sm = (uint32_t)__cvta_generic_to_shared(h1b);
    const uint32_t h2sm = (uint32_t)__cvta_generic_to_shared(h2b);

    if (tid == 0) { mbar_init(mb1, 1); mbar_init(mb2, 1); }

    // ---- stage weights in pass order ----
    // row r = w*24 + phase*12 + k*4 + g ; jloc = w*2 + (g>>1)
    // phase A: g even -> Whh_low (h1 operand), g odd -> Wih_low[:,256:] (h2)
    // phase B: g even -> Wih_high (h1' operand), g odd -> Whh_high (h2)
    for (int i = tid; i < 192 * 64; i += 256) {
        int c4 = i & 63, r = i >> 6;
        int w = r / 24, rem = r % 24;
        int phase = rem / 12, rem2 = rem % 12, k = rem2 >> 2, g = rem2 & 3;
        int jloc = w * 2 + (g >> 1);
        int grow = k * 256 + jbase + jloc;
        const float* src;
        if (phase == 0)
            src = (g & 1) ? Wih_low  + (size_t)grow * 512 + 256
                          : Whh_low  + (size_t)grow * 256;
        else
            src = (g & 1) ? Whh_high + (size_t)grow * 256
                          : Wih_high + (size_t)grow * 256;
        ((float4*)Wsm)[i] = *(const float4*)(src + c4 * 4);
    }
    // ---- stage Gx slice: gxs[t][k*16+s] = Gx[t*768 + k*256 + jbase + s] ----
    for (int i = tid; i < TSTEPS * 48; i += 256) {
        int t = i / 48, r = i % 48, k = r >> 4, s = r & 15;
        gxs[i] = Gx[t * 768 + k * 256 + jbase + s];
    }
    for (int i = tid; i < 512; i += 256) { h1b[i] = 0.f; h2b[i] = 0.f; }
    __syncthreads();
    cluster_sync_dev();

    const int jm = jbase + warp * 2 + (lane >> 4);   // this lane's j
    const int jl = warp * 2 + (lane >> 4);           // local j (for gxs)
    const int base16 = lane & 16;                    // shfl src base
    const int rank = lane & 15;

    // biases for this lane's j
    const float bhl0 = bhh_low [0 * 256 + jm];
    const float bhl1 = bhh_low [1 * 256 + jm];
    const float bhl2 = bhh_low [2 * 256 + jm];
    const float cb0  = bih_high[0 * 256 + jm] + bhh_high[0 * 256 + jm];
    const float cb1  = bih_high[1 * 256 + jm] + bhh_high[1 * 256 + jm];
    const float bi22 = bih_high[2 * 256 + jm];
    const float bh22 = bhh_high[2 * 256 + jm];

    const float* myrowA = Wsm + (size_t)(warp * 24 + grp) * 256;
    const float* myrowB = myrowA + 12 * 256;

    float4 o[8];   // this lane's operand chunks

    for (int t = 0; t < TSTEPS; ++t) {
        const int cur = t & 1, nxt = cur ^ 1;
        const uint32_t par = (uint32_t)(t & 1);
        if (tid == 0) { mbar_expect_tx(mb1, TXB); mbar_expect_tx(mb2, TXB); }

        const float* h1c = h1b + cur * 256;
        const float* h2c = h2b + cur * 256;

        // phase A operand: ODD groups h2c (kept through phase B), EVEN h1c
        {
            const float4* ov = (const float4*)((grp & 1) ? h2c : h1c) + sub;
#pragma unroll
            for (int m = 0; m < 8; ++m) o[m] = ov[m * 8];
        }
        const float h1prev = h1c[jm];
        const float h2prev = h2c[jm];

        float accA[3];
#pragma unroll
        for (int k = 0; k < 3; ++k) {
            const float4* w4 = (const float4*)(myrowA + k * 1024) + sub;
            float a = 0.f;
#pragma unroll
            for (int m = 0; m < 8; ++m) {
                float4 w = w4[m * 8];
                a += w.x * o[m].x + w.y * o[m].y + w.z * o[m].z + w.w * o[m].w;
            }
            a += __shfl_xor_sync(0xFFFFFFFFu, a, 4);
            a += __shfl_xor_sync(0xFFFFFFFFu, a, 2);
            a += __shfl_xor_sync(0xFFFFFFFFu, a, 1);
            accA[k] = a;
        }

        const float gx0 = gxs[t * 48 +  0 + jl];
        const float gx1 = gxs[t * 48 + 16 + jl];
        const float gx2 = gxs[t * 48 + 32 + jl];

        // group base16   = even group -> Whh_low part (B_k)
        // group base16+8 = odd  group -> Wih_low_h2 part (A_k)
        float A0 = __shfl_sync(0xFFFFFFFFu, accA[0], base16)
                 + __shfl_sync(0xFFFFFFFFu, accA[0], base16 + 8);
        float A1 = __shfl_sync(0xFFFFFFFFu, accA[1], base16)
                 + __shfl_sync(0xFFFFFFFFu, accA[1], base16 + 8);
        float A2 = __shfl_sync(0xFFFFFFFFu, accA[2], base16 + 8);  // Wih (i_n)
        float B2 = __shfl_sync(0xFFFFFFFFu, accA[2], base16);      // Whh (h_n)

        float r = sigf(gx0 + A0 + bhl0);
        float z = sigf(gx1 + A1 + bhl1);
        float n = tanhf(gx2 + A2 + r * (bhl2 + B2));
        float h1n = (1.f - z) * n + z * h1prev;

        // broadcast h1n: the 16 lanes of this j each hit one rank
        {
            uint32_t slot = h1sm + (uint32_t)(nxt * 256 + jm) * 4u;
            st_async_b32(mapa_sh(slot, rank), mapa_sh(mb1, rank), h1n);
        }
        if (rank == 0) h1out[t * 256 + jm] = h1n;

        mbar_wait_cluster(mb1, par);

        // phase B operand: even groups reload h1n; odd groups keep h2c
        if (!(grp & 1)) {
            const float4* nv = (const float4*)(h1b + nxt * 256) + sub;
#pragma unroll
            for (int m = 0; m < 8; ++m) o[m] = nv[m * 8];
        }

        float accB[3];
#pragma unroll
        for (int k = 0; k < 3; ++k) {
            const float4* w4 = (const float4*)(myrowB + k * 1024) + sub;
            float a = 0.f;
#pragma unroll
            for (int m = 0; m < 8; ++m) {
                float4 w = w4[m * 8];
                a += w.x * o[m].x + w.y * o[m].y + w.z * o[m].z + w.w * o[m].w;
            }
            a += __shfl_xor_sync(0xFFFFFFFFu, a, 4);
            a += __shfl_xor_sync(0xFFFFFFFFu, a, 2);
            a += __shfl_xor_sync(0xFFFFFFFFu, a, 1);
            accB[k] = a;
        }

        // group base16 = even -> Wih_high (i gates); base16+8 = odd -> Whh_high
        float G0 = __shfl_sync(0xFFFFFFFFu, accB[0], base16)
                 + __shfl_sync(0xFFFFFFFFu, accB[0], base16 + 8);
        float G1 = __shfl_sync(0xFFFFFFFFu, accB[1], base16)
                 + __shfl_sync(0xFFFFFFFFu, accB[1], base16 + 8);
        float G2 = __shfl_sync(0xFFFFFFFFu, accB[2], base16);      // Wih (i_n)
        float F2 = __shfl_sync(0xFFFFFFFFu, accB[2], base16 + 8);  // Whh (h_n)

        float r2 = sigf(G0 + cb0);
        float z2 = sigf(G1 + cb1);
        float n2 = tanhf(G2 + bi22 + r2 * (F2 + bh22));
        float h2n = (1.f - z2) * n2 + z2 * h2prev;

        {
            uint32_t slot = h2sm + (uint32_t)(nxt * 256 + jm) * 4u;
            st_async_b32(mapa_sh(slot, rank), mapa_sh(mb2, rank), h2n);
        }
        mbar_wait_cluster(mb2, par);
    }
    cluster_sync_dev();
}

// ---------------------------------------------------------------------------
// Fallback scan (portable 8-CTA cluster, bf16 weights) — round-2 design.
// ---------------------------------------------------------------------------
__device__ __forceinline__ float rowdot(const __nv_bfloat16* __restrict__ row, int lane,
                                        float4 ha, float4 hb) {
    uint4 u = ((const uint4*)row)[lane];
    float2 a = __bfloat1622float2(*(const __nv_bfloat162*)&u.x);
    float2 b = __bfloat1622float2(*(const __nv_bfloat162*)&u.y);
    float2 c = __bfloat1622float2(*(const __nv_bfloat162*)&u.z);
    float2 d = __bfloat1622float2(*(const __nv_bfloat162*)&u.w);
    float s = a.x * ha.x + a.y * ha.y + b.x * ha.z + b.y * ha.w
            + c.x * hb.x + c.y * hb.y + d.x * hb.z + d.y * hb.w;
#pragma unroll
    for (int o = 16; o; o >>= 1) s += __shfl_xor_sync(0xFFFFFFFFu, s, o);
    return s;
}

__global__ void __launch_bounds__(256, 1) scan8_kernel(
    const float* __restrict__ Wih_low, const float* __restrict__ Whh_low,
    const float* __restrict__ bhh_low,
    const float* __restrict__ Wih_high, const float* __restrict__ Whh_high,
    const float* __restrict__ bih_high, const float* __restrict__ bhh_high,
    const float* __restrict__ Gx, float* __restrict__ h1out)
{
    constexpr int NCTA = 8, S = 32, SP = 4;
    constexpr int WELEMS = 4 * 3 * S * 256;
    constexpr uint32_t TXB = 256 * 4;

    extern __shared__ unsigned char smraw[];
    __nv_bfloat16* Wsm = (__nv_bfloat16*)smraw;
    float* h1b = (float*)(smraw + (size_t)WELEMS * 2);
    float* h2b = h1b + 512;
    unsigned long long* mbars = (unsigned long long*)(h2b + 512);

    const int tid = threadIdx.x, lane = tid & 31, warp = tid >> 5;
    const int cta = blockIdx.x, jbase = cta * S;
    const uint32_t mb1 = (uint32_t)__cvta_generic_to_shared(mbars + 0);
    const uint32_t mb2 = (uint32_t)__cvta_generic_to_shared(mbars + 1);
    const uint32_t h1sm = (uint32_t)__cvta_generic_to_shared(h1b);
    const uint32_t h2sm = (uint32_t)__cvta_generic_to_shared(h2b);

    if (tid == 0) { mbar_init(mb1, 1); mbar_init(mb2, 1); }
    {
        const int N4 = WELEMS / 4;
        for (int i = tid; i < N4; i += 256) {
            int c4 = i & 63, rr = i >> 6;
            int s = rr % S, g = (rr / S) % 3, m = rr / (3 * S);
            int grow = g * 256 + jbase + s;
            const float* src;
            if (m == 0)      src = Wih_low  + (size_t)grow * 512 + 256 + c4 * 4;
            else if (m == 1) src = Whh_low  + (size_t)grow * 256 + c4 * 4;
            else if (m == 2) src = Wih_high + (size_t)grow * 256 + c4 * 4;
            else             src = Whh_high + (size_t)grow * 256 + c4 * 4;
            float4 v = *(const float4*)src;
            __nv_bfloat16* dst = Wsm + (size_t)rr * 256 + c4 * 4;
            dst[0] = (__nv_bfloat16)v.x; dst[1] = (__nv_bfloat16)v.y;
            dst[2] = (__nv_bfloat16)v.z; dst[3] = (__nv_bfloat16)v.w;
        }
    }
    for (int i = tid; i < 512; i += 256) { h1b[i] = 0.f; h2b[i] = 0.f; }
    __syncthreads();
    cluster_sync_dev();

    float bhl[SP][3], bi2[SP][3], bh2[SP][3];
    int js[SP];
#pragma unroll
    for (int p = 0; p < SP; p++) {
        int s = warp * SP + p; js[p] = jbase + s;
#pragma unroll
        for (int g = 0; g < 3; g++) {
            bhl[p][g] = bhh_low [g * 256 + js[p]];
            bi2[p][g] = bih_high[g * 256 + js[p]];
            bh2[p][g] = bhh_high[g * 256 + js[p]];
        }
    }

    for (int t = 0; t < TSTEPS; ++t) {
        const int cur = t & 1, nxt = cur ^ 1;
        const uint32_t par = (uint32_t)(t & 1);
        if (tid == 0) { mbar_expect_tx(mb1, TXB); mbar_expect_tx(mb2, TXB); }
        const float* h1c = h1b + cur * 256;
        const float* h2c = h2b + cur * 256;

        float gx[SP][3];
#pragma unroll
        for (int p = 0; p < SP; p++)
#pragma unroll
            for (int g = 0; g < 3; g++)
                gx[p][g] = __ldg(Gx + t * 768 + g * 256 + js[p]);

        float4 h1a = ((const float4*)h1c)[2 * lane], h1v = ((const float4*)h1c)[2 * lane + 1];
        float4 h2a = ((const float4*)h2c)[2 * lane], h2v = ((const float4*)h2c)[2 * lane + 1];

        float F[SP][3], h1n[SP];
#pragma unroll
        for (int p = 0; p < SP; p++) {
            int s = warp * SP + p;
            float A0 = rowdot(Wsm + ((size_t)((0 * 3 + 0) * S + s)) * 256, lane, h2a, h2v);
            float A1 = rowdot(Wsm + ((size_t)((0 * 3 + 1) * S + s)) * 256, lane, h2a, h2v);
            float A2 = rowdot(Wsm + ((size_t)((0 * 3 + 2) * S + s)) * 256, lane, h2a, h2v);
            float B0 = rowdot(Wsm + ((size_t)((1 * 3 + 0) * S + s)) * 256, lane, h1a, h1v);
            float B1 = rowdot(Wsm + ((size_t)((1 * 3 + 1) * S + s)) * 256, lane, h1a, h1v);
            float B2 = rowdot(Wsm + ((size_t)((1 * 3 + 2) * S + s)) * 256, lane, h1a, h1v);
            F[p][0]  = rowdot(Wsm + ((size_t)((3 * 3 + 0) * S + s)) * 256, lane, h2a, h2v);
            F[p][1]  = rowdot(Wsm + ((size_t)((3 * 3 + 1) * S + s)) * 256, lane, h2a, h2v);
            F[p][2]  = rowdot(Wsm + ((size_t)((3 * 3 + 2) * S + s)) * 256, lane, h2a, h2v);
            float r = sigf(gx[p][0] + A0 + bhl[p][0] + B0);
            float z = sigf(gx[p][1] + A1 + bhl[p][1] + B1);
            float n = tanhf(gx[p][2] + A2 + r * (bhl[p][2] + B2));
            h1n[p] = (1.f - z) * n + z * h1c[js[p]];
        }
#pragma unroll
        for (int p = 0; p < SP; p++) {
            if (lane >= p * NCTA && lane < (p + 1) * NCTA) {
                int rk = lane - p * NCTA;
                uint32_t slot = h1sm + (uint32_t)(nxt * 256 + js[p]) * 4u;
                st_async_b32(mapa_sh(slot, rk), mapa_sh(mb1, rk), h1n[p]);
            }
            if (lane == p) h1out[t * 256 + js[p]] = h1n[p];
        }
        mbar_wait_cluster(mb1, par);

        const float* h1nv = h1b + nxt * 256;
        float4 n1a = ((const float4*)h1nv)[2 * lane], n1v = ((const float4*)h1nv)[2 * lane + 1];
#pragma unroll
        for (int p = 0; p < SP; p++) {
            int s = warp * SP + p;
            float G0 = rowdot(Wsm + ((size_t)((2 * 3 + 0) * S + s)) * 256, lane, n1a, n1v);
            float G1 = rowdot(Wsm + ((size_t)((2 * 3 + 1) * S + s)) * 256, lane, n1a, n1v);
            float G2 = rowdot(Wsm + ((size_t)((2 * 3 + 2) * S + s)) * 256, lane, n1a, n1v);
            float r2 = sigf(G0 + bi2[p][0] + F[p][0] + bh2[p][0]);
            float z2 = sigf(G1 + bi2[p][1] + F[p][1] + bh2[p][1]);
            float n2 = tanhf(G2 + bi2[p][2] + r2 * (F[p][2] + bh2[p][2]));
            float h2n = (1.f - z2) * n2 + z2 * h2c[js[p]];
            if (lane >= p * NCTA && lane < (p + 1) * NCTA) {
                int rk = lane - p * NCTA;
                uint32_t slot = h2sm + (uint32_t)(nxt * 256 + js[p]) * 4u;
                st_async_b32(mapa_sh(slot, rk), mapa_sh(mb2, rk), h2n);
            }
        }
        mbar_wait_cluster(mb2, par);
    }
    cluster_sync_dev();
}

// ---------------------------------------------------------------------------
// Post kernel. grid (4, TSTEPS).
// ---------------------------------------------------------------------------
__global__ void __launch_bounds__(256) post_kernel(
    const float* __restrict__ h1out,
    const float* __restrict__ W2v, const float* __restrict__ b2v,
    const float* __restrict__ W2m, const float* __restrict__ b2m,
    float* __restrict__ out)
{
    int t = blockIdx.y;
    __shared__ float fe[256];
    int tid = threadIdx.x, lane = tid & 31, warp = tid >> 5;

    fe[tid] = eluf(h1out[t * 256 + tid]);
    __syncthreads();

    float* vout = out;
    float* mout = out + TSTEPS * 768;

    int r0 = blockIdx.x * 192 + warp * 24;
#pragma unroll
    for (int i = r0; i < r0 + 24; ++i) {
        float s = 0.f;
#pragma unroll
        for (int k = lane; k < 128; k += 32) s += W2v[i * 128 + k] * fe[k];
#pragma unroll
        for (int o = 16; o; o >>= 1) s += __shfl_xor_sync(0xFFFFFFFFu, s, o);
        if (lane == 0) vout[t * 768 + i] = sigf(s + b2v[i]);
    }
    if (blockIdx.x == 0 && warp < 2) {
        int i = warp;
        float s = 0.f;
#pragma unroll
        for (int k = lane; k < 128; k += 32) s += W2m[i * 128 + k] * fe[128 + k];
#pragma unroll
        for (int o = 16; o; o >>= 1) s += __shfl_xor_sync(0xFFFFFFFFu, s, o);
        if (lane == 0) mout[t * 2 + i] = tanhf(s + b2m[i]);
    }
}

// ---------------------------------------------------------------------------
extern "C" void kernel_launch(void* const* d_in, const int* in_sizes, int n_in,
                              void* d_out, int out_size)
{
    const float* v0       = (const float*)d_in[0];
    const float* m0       = (const float*)d_in[1];
    const float* W1v      = (const float*)d_in[2];
    const float* b1v      = (const float*)d_in[3];
    const float* W1m      = (const float*)d_in[4];
    const float* b1m      = (const float*)d_in[5];
    const float* Wih_low  = (const float*)d_in[6];
    const float* Whh_low  = (const float*)d_in[7];
    const float* bih_low  = (const float*)d_in[8];
    const float* bhh_low  = (const float*)d_in[9];
    const float* Wih_high = (const float*)d_in[10];
    const float* Whh_high = (const float*)d_in[11];
    const float* bih_high = (const float*)d_in[12];
    const float* bhh_high = (const float*)d_in[13];
    const float* W2v      = (const float*)d_in[14];
    const float* b2v      = (const float*)d_in[15];
    const float* W2m      = (const float*)d_in[16];
    const float* b2m      = (const float*)d_in[17];
    float* out = (float*)d_out;

    float *Gx = nullptr, *h1s = nullptr, *fbuf = nullptr;
    cudaGetSymbolAddress((void**)&Gx, g_Gx);
    cudaGetSymbolAddress((void**)&h1s, g_h1);
    cudaGetSymbolAddress((void**)&fbuf, g_f);

    f_kernel <<<dim3(2, TSTEPS), 256>>>(v0, m0, W1v, b1v, W1m, b1m, fbuf);
    gx_kernel<<<dim3(6, TSTEPS), 256>>>(Wih_low, bih_low, fbuf, Gx);

    const size_t smem16 = 196608 + 4096 + (size_t)TSTEPS * 48 * 4 + 64;  // 210368
    const size_t smem8  = 196608 + 4096 + 64;

    cudaFuncSetAttribute(scan16_kernel, cudaFuncAttributeMaxDynamicSharedMemorySize, (int)smem16);
    cudaError_t eNp = cudaFuncSetAttribute(scan16_kernel,
                                           cudaFuncAttributeNonPortableClusterSizeAllowed, 1);

    cudaLaunchConfig_t cfg = {};
    cfg.blockDim = {256, 1, 1};
    cfg.stream = 0;

    int maxC = 0;
    if (eNp == cudaSuccess) {
        cfg.gridDim = {16, 1, 1};
        cfg.dynamicSmemBytes = smem16;
        cudaError_t eq = cudaOccupancyMaxPotentialClusterSize(&maxC, scan16_kernel, &cfg);
        if (eq != cudaSuccess) maxC = 0;
    }

    cudaLaunchAttribute at[1];
    at[0].id = cudaLaunchAttributeClusterDimension;

    if (maxC >= 16) {
        cfg.gridDim = {16, 1, 1};
        cfg.dynamicSmemBytes = smem16;
        at[0].val.clusterDim = {16, 1, 1};
        cfg.attrs = at; cfg.numAttrs = 1;
        cudaLaunchKernelEx(&cfg, scan16_kernel, Wih_low, Whh_low, bhh_low,
                           Wih_high, Whh_high, bih_high, bhh_high,
                           (const float*)Gx, h1s);
    } else {
        cudaFuncSetAttribute(scan8_kernel, cudaFuncAttributeMaxDynamicSharedMemorySize, (int)smem8);
        cfg.gridDim = {8, 1, 1};
        cfg.dynamicSmemBytes = smem8;
        at[0].val.clusterDim = {8, 1, 1};
        cfg.attrs = at; cfg.numAttrs = 1;
        cudaLaunchKernelEx(&cfg, scan8_kernel, Wih_low, Whh_low, bhh_low,
                           Wih_high, Whh_high, bih_high, bhh_high,
                           (const float*)Gx, h1s);
    }

    post_kernel<<<dim3(4, TSTEPS), 256>>>(h1s, W2v, b2v, W2m, b2m, out);
}